// round 7
// baseline (speedup 1.0000x reference)
#include <cuda_runtime.h>
#include <cuda_bf16.h>
#include <math.h>
#include <stdint.h>

#define BATCH   2
#define NNODE   32768
#define DIM     128
#define ZDIM    256
#define OUTD    128
#define HEADS   8
#define NEDGE   262144
#define NODES_TOT (BATCH*NNODE)   /* 65536  */
#define EDGES_TOT (BATCH*NEDGE)   /* 524288 */
#define NEG_SLOPE 0.01f

// ---------------- scratch (static device allocations; no cudaMalloc) ----------------
__device__ float g_att1[NODES_TOT*HEADS];
__device__ float g_att2[NODES_TOT*HEADS];
__device__ float g_v[NODES_TOT*OUTD];
__device__ float g_skip[NODES_TOT*OUTD];
__device__ float g_hidden2[NODES_TOT*OUTD];
__device__ float g_sumv[NODES_TOT*HEADS];   // zero-init; finalize re-zeros (race-free)
__device__ float g_agg[NODES_TOT*OUTD];     // zero-init; finalize re-zeros
__device__ float g_bcat[256];
__device__ float g_Wa[ZDIM*16];
__device__ float g_ba[16];
// bf16 hi/lo split of W^T: [n][k], n<128 -> Wm cols, n>=128 -> Wskip cols
__device__ unsigned short g_Wt_hi[256*256];
__device__ unsigned short g_Wt_lo[256*256];

// ---------------- helpers ----------------
__device__ __forceinline__ uint32_t smem_to_u32(const void* smem_ptr) {
    uint32_t addr;
    asm("{ .reg .u64 tmp; cvta.to.shared.u64 tmp, %1; cvt.u32.u64 %0, tmp; }"
        : "=r"(addr) : "l"(smem_ptr));
    return addr;
}
__device__ __forceinline__ void ldsm4(uint32_t* r, uint32_t addr){
    asm volatile("ldmatrix.sync.aligned.m8n8.x4.shared.b16 {%0,%1,%2,%3}, [%4];"
        : "=r"(r[0]), "=r"(r[1]), "=r"(r[2]), "=r"(r[3]) : "r"(addr));
}
__device__ __forceinline__ void mma_bf16(float* c, const uint32_t* a, uint32_t b0, uint32_t b1){
    asm volatile("mma.sync.aligned.m16n8k16.row.col.f32.bf16.bf16.f32 "
        "{%0,%1,%2,%3}, {%4,%5,%6,%7}, {%8,%9}, {%0,%1,%2,%3};"
        : "+f"(c[0]), "+f"(c[1]), "+f"(c[2]), "+f"(c[3])
        : "r"(a[0]), "r"(a[1]), "r"(a[2]), "r"(a[3]), "r"(b0), "r"(b1));
}
__device__ __forceinline__ void split1(float a, unsigned short& h, unsigned short& l){
    __nv_bfloat16 hb = __float2bfloat16(a);
    __nv_bfloat16 lb = __float2bfloat16(a - __bfloat162float(hb));
    h = __bfloat16_as_ushort(hb); l = __bfloat16_as_ushort(lb);
}
__device__ __forceinline__ uint32_t pack2(unsigned short a, unsigned short b){
    return (uint32_t)a | ((uint32_t)b << 16);
}

// ---------------- weight packing ----------------
__global__ void build_w(const float* __restrict__ Wm, const float* __restrict__ bm,
                        const float* __restrict__ Wskip, const float* __restrict__ bskip,
                        const float* __restrict__ Wa1, const float* __restrict__ ba1,
                        const float* __restrict__ Wa2, const float* __restrict__ ba2){
    int i = blockIdx.x*blockDim.x + threadIdx.x;
    if (i < 256*256){
        int n = i >> 8, k = i & 255;
        float w = (n < OUTD) ? Wm[k*OUTD + n] : Wskip[k*OUTD + (n - OUTD)];
        unsigned short h, l;
        split1(w, h, l);
        g_Wt_hi[i] = h; g_Wt_lo[i] = l;
    }
    if (i < ZDIM*16){
        int k = i >> 4, j = i & 15;
        g_Wa[i] = (j < HEADS) ? Wa1[k*HEADS + j] : Wa2[k*HEADS + (j-HEADS)];
    }
    if (i < 256) g_bcat[i] = (i < OUTD) ? bm[i] : bskip[i-OUTD];
    if (i < 16)  g_ba[i]   = (i < HEADS) ? ba1[i] : ba2[i-HEADS];
}

// ================= node GEMM on mma.sync bf16 (3-term split) =================
// [v | skip](65536x256) = concat(f1,f2)(65536x256) @ Wt^T + bcat
// CTA: 256 threads (8 warps, 2x4), BM=64, BN=256, BK=32 (8 chunks).
// Warp region 32x64. smem rows padded to 40 bf16 (80B) -> conflict-free ldmatrix.
// 2 CTAs/SM co-resident: one computes while the other stages (latency hiding).
#define SM_AHI     0
#define SM_ALO     5120
#define SM_BHI     10240
#define SM_BLO     30720
#define GEMM_SMEM  51200

__global__ void __launch_bounds__(256, 2) gemm_node_mma(const float* __restrict__ f1,
                                                        const float* __restrict__ f2in,
                                                        int use_hidden2){
    const float* f2 = use_hidden2 ? g_hidden2 : f2in;
    extern __shared__ char sm[];
    const uint32_t sb = smem_to_u32(sm);
    const int tid  = threadIdx.x;
    const int lane = tid & 31;
    const int wid  = tid >> 5;
    const int wm   = (wid >> 2) * 32;       // {0, 32}
    const int wn   = (wid & 3) * 64;        // {0, 64, 128, 192}
    const int row0g = blockIdx.x * 64;

    float acc[2][8][4];
    #pragma unroll
    for (int a = 0; a < 2; a++)
        #pragma unroll
        for (int b = 0; b < 8; b++)
            #pragma unroll
            for (int c = 0; c < 4; c++) acc[a][b][c] = 0.0f;

    const int arow = tid >> 2, ac = tid & 3;        // A: 64 rows x 4 col-groups of 8
    const int bn = tid;                              // B: one full 32-col row per thread
    const int grp = lane >> 3, wi = lane & 7;        // ldmatrix lane decomposition

    for (int kc = 0; kc < 8; kc++){
        __syncthreads();
        // ---- stage A chunk: f32 -> bf16 hi/lo ----
        {
            const float* srcb = (kc < 4) ? f1 : f2;
            const int ksrc = (kc & 3) * 32;
            const float* ap = srcb + (size_t)(row0g + arow)*DIM + ksrc + ac*8;
            float4 v0 = *(const float4*)ap;
            float4 v1 = *(const float4*)(ap + 4);
            unsigned short h[8], l[8];
            split1(v0.x, h[0], l[0]); split1(v0.y, h[1], l[1]);
            split1(v0.z, h[2], l[2]); split1(v0.w, h[3], l[3]);
            split1(v1.x, h[4], l[4]); split1(v1.y, h[5], l[5]);
            split1(v1.z, h[6], l[6]); split1(v1.w, h[7], l[7]);
            uint4 hh; hh.x = pack2(h[0],h[1]); hh.y = pack2(h[2],h[3]);
                      hh.z = pack2(h[4],h[5]); hh.w = pack2(h[6],h[7]);
            uint4 ll; ll.x = pack2(l[0],l[1]); ll.y = pack2(l[2],l[3]);
                      ll.z = pack2(l[4],l[5]); ll.w = pack2(l[6],l[7]);
            *(uint4*)(sm + SM_AHI + arow*80 + ac*16) = hh;
            *(uint4*)(sm + SM_ALO + arow*80 + ac*16) = ll;
        }
        // ---- stage B chunk: preconverted bf16 hi/lo, one 32-col row per thread ----
        {
            const uint4* wh = (const uint4*)(g_Wt_hi + bn*256 + kc*32);
            const uint4* wl = (const uint4*)(g_Wt_lo + bn*256 + kc*32);
            uint4 x0 = wh[0], x1 = wh[1], x2 = wh[2], x3 = wh[3];
            uint4 y0 = wl[0], y1 = wl[1], y2 = wl[2], y3 = wl[3];
            char* bh = sm + SM_BHI + bn*80;
            char* bl = sm + SM_BLO + bn*80;
            *(uint4*)(bh)      = x0; *(uint4*)(bh + 16) = x1;
            *(uint4*)(bh + 32) = x2; *(uint4*)(bh + 48) = x3;
            *(uint4*)(bl)      = y0; *(uint4*)(bl + 16) = y1;
            *(uint4*)(bl + 32) = y2; *(uint4*)(bl + 48) = y3;
        }
        __syncthreads();

        #pragma unroll
        for (int ks = 0; ks < 2; ks++){
            const int kb = ks*16;
            uint32_t ah[2][4], al[2][4];
            #pragma unroll
            for (int mt = 0; mt < 2; mt++){
                int r = wm + mt*16 + wi + (grp & 1)*8;
                int c = kb + (grp >> 1)*8;
                uint32_t adr = sb + SM_AHI + r*80 + c*2;
                ldsm4(ah[mt], adr);
                ldsm4(al[mt], adr + (SM_ALO - SM_AHI));
            }
            #pragma unroll
            for (int np = 0; np < 4; np++){
                int n0 = wn + np*16;
                int rb = n0 + wi + (grp >> 1)*8;
                int cb = kb + (grp & 1)*8;
                uint32_t badr = sb + SM_BHI + rb*80 + cb*2;
                uint32_t bh[4], bl[4];
                ldsm4(bh, badr);
                ldsm4(bl, badr + (SM_BLO - SM_BHI));
                #pragma unroll
                for (int mt = 0; mt < 2; mt++){
                    #pragma unroll
                    for (int nt = 0; nt < 2; nt++){
                        float* C = acc[mt][np*2 + nt];
                        mma_bf16(C, ah[mt], bh[nt*2], bh[nt*2+1]);
                        mma_bf16(C, al[mt], bh[nt*2], bh[nt*2+1]);
                        mma_bf16(C, ah[mt], bl[nt*2], bl[nt*2+1]);
                    }
                }
            }
        }
    }

    // ---- epilogue: write v|skip with bias ----
    const int gid = lane >> 2, tc = lane & 3;
    #pragma unroll
    for (int mt = 0; mt < 2; mt++){
        int r0 = row0g + wm + mt*16 + gid;
        #pragma unroll
        for (int np = 0; np < 4; np++){
            #pragma unroll
            for (int nt = 0; nt < 2; nt++){
                int col = wn + np*16 + nt*8 + tc*2;
                float* dst = (col < 128) ? g_v : g_skip;
                int cl = col & 127;
                float b0 = g_bcat[col], b1 = g_bcat[col + 1];
                float* C = acc[mt][np*2 + nt];
                float2 o0; o0.x = C[0] + b0; o0.y = C[1] + b1;
                float2 o1; o1.x = C[2] + b0; o1.y = C[3] + b1;
                *(float2*)(dst + (size_t)r0*OUTD + cl)       = o0;
                *(float2*)(dst + (size_t)(r0+8)*OUTD + cl)   = o1;
            }
        }
    }
}

// ---------------- attention-vector GEMM: [att1 | att2] = z @ Wa + ba ----------------
__global__ void __launch_bounds__(256) gemm_att(const float* __restrict__ f1,
                                                const float* __restrict__ f2in,
                                                int use_hidden2){
    const float* f2 = use_hidden2 ? g_hidden2 : f2in;
    __shared__ float As2[128][36];
    __shared__ float Bs[32][16];
    const int t = threadIdx.x;
    const int row0 = blockIdx.x * 128;
    const int my = t >> 1, tx = t & 1;
    float acc[8] = {0,0,0,0,0,0,0,0};

    for (int half = 0; half < 2; half++){
        const float* base = half ? f2 : f1;
        for (int kc = 0; kc < DIM; kc += 32){
            #pragma unroll
            for (int i = 0; i < 4; i++){
                int id = t + 256*i;
                int r = id >> 3, q = id & 7;
                float4 g = *(const float4*)(base + (size_t)(row0 + r)*DIM + kc + q*4);
                *(float4*)(&As2[r][q*4]) = g;
            }
            if (t < 128){
                int kk = t >> 2, j4 = (t & 3)*4;
                *(float4*)(&Bs[kk][j4]) = *(const float4*)(g_Wa + (half*DIM + kc + kk)*16 + j4);
            }
            __syncthreads();
            #pragma unroll
            for (int kk = 0; kk < 32; kk++){
                float a = As2[my][kk];
                float4 b0 = *(float4*)(&Bs[kk][tx*8]);
                float4 b1 = *(float4*)(&Bs[kk][tx*8 + 4]);
                acc[0] = fmaf(a, b0.x, acc[0]); acc[1] = fmaf(a, b0.y, acc[1]);
                acc[2] = fmaf(a, b0.z, acc[2]); acc[3] = fmaf(a, b0.w, acc[3]);
                acc[4] = fmaf(a, b1.x, acc[4]); acc[5] = fmaf(a, b1.y, acc[5]);
                acc[6] = fmaf(a, b1.z, acc[6]); acc[7] = fmaf(a, b1.w, acc[7]);
            }
            __syncthreads();
        }
    }

    int row = row0 + my;
    #pragma unroll
    for (int jj = 0; jj < 8; jj++){
        int j = tx*8 + jj;
        float v = acc[jj] + g_ba[j];
        if (j < HEADS) g_att1[row*HEADS + j] = v;
        else           g_att2[row*HEADS + (j-HEADS)] = v;
    }
}

// ---------------- fused edge pass (cfg): logits -> exp -> scatter sum & exp*v ----------------
// Softmax computed WITHOUT max-shift (logits bounded; exp safe in fp32);
// normalization deferred to finalize (agg/sumv). One pass over edges.
__global__ void __launch_bounds__(256) edge_pass_cfg(const int* __restrict__ idx){
    int gt = blockIdx.x*blockDim.x + threadIdx.x;
    int e = gt >> 5, lane = gt & 31;
    if (e >= EDGES_TOT) return;
    int s = idx[2*e], tg = idx[2*e + 1];
    int base = (e >= NEDGE) ? NNODE : 0;
    float ex = 0.0f;
    if (lane < HEADS){
        float l = g_att1[(base+s)*HEADS + lane] + g_att2[(base+tg)*HEADS + lane];
        l = (l > 0.0f) ? l : NEG_SLOPE*l;
        ex = __expf(l);
        atomicAdd(&g_sumv[(base+tg)*HEADS + lane], ex);
    }
    float c = __shfl_sync(0xffffffffu, ex, lane >> 2);
    float4 v4 = *(const float4*)(g_v + (size_t)(base+s)*OUTD + lane*4);
    float4 m; m.x = c*v4.x; m.y = c*v4.y; m.z = c*v4.z; m.w = c*v4.w;
    float* p = g_agg + (size_t)(base+tg)*OUTD + lane*4;
    asm volatile("red.global.add.v4.f32 [%0], {%1,%2,%3,%4};"
                 :: "l"(p), "f"(m.x), "f"(m.y), "f"(m.z), "f"(m.w) : "memory");
}

// ---------------- fused edge pass (gkt): + edge-feature logits ----------------
__global__ void __launch_bounds__(256) edge_pass_gkt(const float* __restrict__ ef,
                                                     const int* __restrict__ idx,
                                                     const float* __restrict__ Wae,
                                                     const float* __restrict__ bae){
    __shared__ float sWt[8][132];   // transposed Wae: [h][k]
    for (int i = threadIdx.x; i < DIM*HEADS; i += 256){
        int k = i & 127, h = i >> 7;
        sWt[h][k] = Wae[k*HEADS + h];
    }
    __syncthreads();
    int e = (blockIdx.x*256 + threadIdx.x) >> 5;
    int lane = threadIdx.x & 31;
    if (e >= EDGES_TOT) return;

    float4 x = *(const float4*)(ef + (size_t)e*DIM + lane*4);
    float p8[8];
    #pragma unroll
    for (int h = 0; h < 8; h++){
        float4 w = *(const float4*)(&sWt[h][lane*4]);
        p8[h] = x.x*w.x + x.y*w.y + x.z*w.z + x.w*w.w;
    }
    float ae = 0.0f;
    #pragma unroll
    for (int h = 0; h < 8; h++){
        float v = p8[h];
        v += __shfl_xor_sync(0xffffffffu, v, 16);
        v += __shfl_xor_sync(0xffffffffu, v, 8);
        v += __shfl_xor_sync(0xffffffffu, v, 4);
        v += __shfl_xor_sync(0xffffffffu, v, 2);
        v += __shfl_xor_sync(0xffffffffu, v, 1);
        if (lane == h) ae = v;
    }
    int s = idx[2*e], tg = idx[2*e + 1];
    int base = (e >= NEDGE) ? NNODE : 0;
    float ex = 0.0f;
    if (lane < HEADS){
        float l = g_att1[(base+s)*HEADS + lane] + g_att2[(base+tg)*HEADS + lane]
                  + ae + bae[lane];
        l = (l > 0.0f) ? l : NEG_SLOPE*l;
        ex = __expf(l);
        atomicAdd(&g_sumv[(base+tg)*HEADS + lane], ex);
    }
    float c = __shfl_sync(0xffffffffu, ex, lane >> 2);
    float4 v4 = *(const float4*)(g_v + (size_t)(base+s)*OUTD + lane*4);
    float4 m; m.x = c*v4.x; m.y = c*v4.y; m.z = c*v4.z; m.w = c*v4.w;
    float* p = g_agg + (size_t)(base+tg)*OUTD + lane*4;
    asm volatile("red.global.add.v4.f32 [%0], {%1,%2,%3,%4};"
                 :: "l"(p), "f"(m.x), "f"(m.y), "f"(m.z), "f"(m.w) : "memory");
}

// ---------------- finalize: relu(agg/sumv + skip); reset agg/sumv race-free ----------------
// Thread i handles float4 i of g_agg. Readers of g_sumv[node*8+head] are exactly
// the 4 consecutive threads i = node*32 + head*4 + {0..3} (one warp). So: read,
// __syncwarp(), then lane (i&3)==0 zeroes that entry. No cross-block hazard.
__global__ void finalize(float* __restrict__ dstin, int to_hidden2){
    int i = blockIdx.x*blockDim.x + threadIdx.x;
    if (i >= NODES_TOT*OUTD/4) return;
    float* dst = to_hidden2 ? g_hidden2 : dstin;
    int node = i >> 5;                 // 32 float4 per node row
    int head = (i & 31) >> 2;          // 4 float4 per 16-wide head
    float sv = g_sumv[node*HEADS + head];
    __syncwarp();
    if ((i & 3) == 0) g_sumv[node*HEADS + head] = 0.0f;
    float inv = (sv != 0.0f) ? (1.0f / sv) : 0.0f;
    float4 a = ((const float4*)g_agg)[i];
    float4 s = ((const float4*)g_skip)[i];
    float4 o;
    o.x = fmaxf(fmaf(a.x, inv, s.x), 0.0f);
    o.y = fmaxf(fmaf(a.y, inv, s.y), 0.0f);
    o.z = fmaxf(fmaf(a.z, inv, s.z), 0.0f);
    o.w = fmaxf(fmaf(a.w, inv, s.w), 0.0f);
    ((float4*)dst)[i] = o;
    float4 z; z.x = 0.0f; z.y = 0.0f; z.z = 0.0f; z.w = 0.0f;
    ((float4*)g_agg)[i] = z;
}

// ---------------- launch ----------------
extern "C" void kernel_launch(void* const* d_in, const int* in_sizes, int n_in,
                              void* d_out, int out_size){
    const float* node_fts     = (const float*)d_in[0];
    const float* gkt_edge_fts = (const float*)d_in[1];
    const float* hidden       = (const float*)d_in[2];
    const int*   cfg_idx      = (const int*)d_in[3];
    const int*   gkt_idx      = (const int*)d_in[4];
    const float* Wm    = (const float*)d_in[5];
    const float* bm    = (const float*)d_in[6];
    const float* Wskip = (const float*)d_in[7];
    const float* bskip = (const float*)d_in[8];
    const float* Wa1   = (const float*)d_in[9];
    const float* ba1   = (const float*)d_in[10];
    const float* Wa2   = (const float*)d_in[11];
    const float* ba2   = (const float*)d_in[12];
    const float* Wae   = (const float*)d_in[13];
    const float* bae   = (const float*)d_in[14];
    float* out = (float*)d_out;

    static int smem_set = 0;
    if (!smem_set){
        cudaFuncSetAttribute(gemm_node_mma, cudaFuncAttributeMaxDynamicSharedMemorySize, GEMM_SMEM);
        smem_set = 1;
    }

    const int TB = 256;

    build_w<<<(256*256 + TB-1)/TB, TB>>>(Wm, bm, Wskip, bskip, Wa1, ba1, Wa2, ba2);   // 0

    // ===== stage 1 (cfg): z = [node_fts | hidden] =====
    gemm_att<<<NODES_TOT/128, TB>>>(node_fts, hidden, 0);                              // 1
    gemm_node_mma<<<NODES_TOT/64, 256, GEMM_SMEM>>>(node_fts, hidden, 0);              // 2
    edge_pass_cfg<<<(EDGES_TOT*32)/TB, TB>>>(cfg_idx);                                 // 3 <- ncu capture
    finalize<<<(NODES_TOT*OUTD/4)/TB, TB>>>(out, 1);   // -> g_hidden2                 // 4

    // ===== stage 2 (gkt): z = [node_fts | cfg_hidden] =====
    gemm_att<<<NODES_TOT/128, TB>>>(node_fts, nullptr, 1);                             // 5
    gemm_node_mma<<<NODES_TOT/64, 256, GEMM_SMEM>>>(node_fts, nullptr, 1);             // 6
    edge_pass_gkt<<<(EDGES_TOT*32)/TB, TB>>>(gkt_edge_fts, gkt_idx, Wae, bae);         // 7
    finalize<<<(NODES_TOT*OUTD/4)/TB, TB>>>(out, 0);   // -> d_out                     // 8
}

// round 8
// speedup vs baseline: 1.2047x; 1.2047x over previous
#include <cuda_runtime.h>
#include <cuda_bf16.h>
#include <math.h>
#include <stdint.h>

#define BATCH   2
#define NNODE   32768
#define DIM     128
#define ZDIM    256
#define OUTD    128
#define HEADS   8
#define NEDGE   262144
#define NODES_TOT (BATCH*NNODE)   /* 65536  */
#define EDGES_TOT (BATCH*NEDGE)   /* 524288 */
#define NEG_SLOPE 0.01f

// ---------------- scratch (static device allocations; no cudaMalloc) ----------------
__device__ float g_att1[NODES_TOT*HEADS];
__device__ float g_att2[NODES_TOT*HEADS];
__device__ float g_v[NODES_TOT*OUTD];
__device__ float g_skip[NODES_TOT*OUTD];
__device__ float g_hidden2[NODES_TOT*OUTD];
__device__ float g_sumv[NODES_TOT*HEADS];   // zero-init; finalize re-zeros (race-free)
__device__ float g_agg[NODES_TOT*OUTD];     // zero-init; finalize re-zeros
__device__ float g_bcat[256];
__device__ float g_Wa[ZDIM*16];
__device__ float g_ba[16];
// bf16 hi/lo split of W^T: [n][k], n<128 -> Wm cols, n>=128 -> Wskip cols
__device__ unsigned short g_Wt_hi[256*256];
__device__ unsigned short g_Wt_lo[256*256];

// ---------------- helpers ----------------
__device__ __forceinline__ uint32_t smem_to_u32(const void* smem_ptr) {
    uint32_t addr;
    asm("{ .reg .u64 tmp; cvta.to.shared.u64 tmp, %1; cvt.u32.u64 %0, tmp; }"
        : "=r"(addr) : "l"(smem_ptr));
    return addr;
}
__device__ __forceinline__ void ldsm4(uint32_t* r, uint32_t addr){
    asm volatile("ldmatrix.sync.aligned.m8n8.x4.shared.b16 {%0,%1,%2,%3}, [%4];"
        : "=r"(r[0]), "=r"(r[1]), "=r"(r[2]), "=r"(r[3]) : "r"(addr));
}
__device__ __forceinline__ void mma_bf16(float* c, const uint32_t* a, uint32_t b0, uint32_t b1){
    asm volatile("mma.sync.aligned.m16n8k16.row.col.f32.bf16.bf16.f32 "
        "{%0,%1,%2,%3}, {%4,%5,%6,%7}, {%8,%9}, {%0,%1,%2,%3};"
        : "+f"(c[0]), "+f"(c[1]), "+f"(c[2]), "+f"(c[3])
        : "r"(a[0]), "r"(a[1]), "r"(a[2]), "r"(a[3]), "r"(b0), "r"(b1));
}
__device__ __forceinline__ void split1(float a, unsigned short& h, unsigned short& l){
    __nv_bfloat16 hb = __float2bfloat16(a);
    __nv_bfloat16 lb = __float2bfloat16(a - __bfloat162float(hb));
    h = __bfloat16_as_ushort(hb); l = __bfloat16_as_ushort(lb);
}
__device__ __forceinline__ uint32_t pack2(unsigned short a, unsigned short b){
    return (uint32_t)a | ((uint32_t)b << 16);
}
__device__ __forceinline__ void cp16(uint32_t dst, const void* src){
    asm volatile("cp.async.ca.shared.global [%0], [%1], 16;" :: "r"(dst), "l"(src));
}
#define CP_COMMIT() asm volatile("cp.async.commit_group;" ::: "memory")
#define CP_WAIT0()  asm volatile("cp.async.wait_group 0;" ::: "memory")

// ---------------- weight packing ----------------
__global__ void build_w(const float* __restrict__ Wm, const float* __restrict__ bm,
                        const float* __restrict__ Wskip, const float* __restrict__ bskip,
                        const float* __restrict__ Wa1, const float* __restrict__ ba1,
                        const float* __restrict__ Wa2, const float* __restrict__ ba2){
    int i = blockIdx.x*blockDim.x + threadIdx.x;
    if (i < 256*256){
        int n = i >> 8, k = i & 255;
        float w = (n < OUTD) ? Wm[k*OUTD + n] : Wskip[k*OUTD + (n - OUTD)];
        unsigned short h, l;
        split1(w, h, l);
        g_Wt_hi[i] = h; g_Wt_lo[i] = l;
    }
    if (i < ZDIM*16){
        int k = i >> 4, j = i & 15;
        g_Wa[i] = (j < HEADS) ? Wa1[k*HEADS + j] : Wa2[k*HEADS + (j-HEADS)];
    }
    if (i < 256) g_bcat[i] = (i < OUTD) ? bm[i] : bskip[i-OUTD];
    if (i < 16)  g_ba[i]   = (i < HEADS) ? ba1[i] : ba2[i-HEADS];
}

// ================= node GEMM on mma.sync bf16 (3-term split), cp.async pipelined ===========
// [v | skip](65536x256) = concat(f1,f2)(65536x256) @ Wt^T + bcat
// CTA: 512 threads (16 warps, 4x4), BM=128, BN=256, BK=32 (8 chunks).
// B double-buffered via cp.async (prefetch chunk kc+1 during compute of kc);
// A prefetched to registers at iteration top, converted+STS between syncs.
#define SM_AHI     0
#define SM_ALO     10240
#define SM_B0      20480      /* each B buf: hi at +0 (20480B), lo at +20480 */
#define B_BUF_SZ   40960
#define GEMM_SMEM  102400

__global__ void __launch_bounds__(512) gemm_node_mma(const float* __restrict__ f1,
                                                     const float* __restrict__ f2in,
                                                     int use_hidden2){
    const float* f2 = use_hidden2 ? g_hidden2 : f2in;
    extern __shared__ char sm[];
    const uint32_t sb = smem_to_u32(sm);
    const int tid  = threadIdx.x;
    const int lane = tid & 31;
    const int wid  = tid >> 5;
    const int wm   = (wid >> 2) * 32;       // {0,32,64,96}
    const int wn   = (wid & 3) * 64;        // {0,64,128,192}
    const int row0g = blockIdx.x * 128;

    float acc[2][8][4];
    #pragma unroll
    for (int a = 0; a < 2; a++)
        #pragma unroll
        for (int b = 0; b < 8; b++)
            #pragma unroll
            for (int c = 0; c < 4; c++) acc[a][b][c] = 0.0f;

    const int arow = tid >> 2, ac = tid & 3;     // A: 128 rows x 4 col-groups of 8 floats
    const int bn = tid >> 1,  hb = tid & 1;      // B: 256 rows x 2 half-rows (32B each)
    const int grp = lane >> 3, wi = lane & 7;    // ldmatrix lane decomposition

    // ---- prologue: cp.async B chunk 0; prefetch A chunk 0 into regs ----
    {
        uint32_t bdst = sb + SM_B0 + bn*80 + hb*32;
        const unsigned short* src_h = g_Wt_hi + bn*256 + 0*32 + hb*16;
        const unsigned short* src_l = g_Wt_lo + bn*256 + 0*32 + hb*16;
        cp16(bdst,             src_h);
        cp16(bdst + 16,        src_h + 8);
        cp16(bdst + 20480,     src_l);
        cp16(bdst + 20480 + 16,src_l + 8);
        CP_COMMIT();
    }
    float4 apre0, apre1;
    {
        const float* ap = f1 + (size_t)(row0g + arow)*DIM + 0 + ac*8;
        apre0 = *(const float4*)ap; apre1 = *(const float4*)(ap + 4);
    }

    for (int kc = 0; kc < 8; kc++){
        const uint32_t bbase = sb + SM_B0 + (kc & 1)*B_BUF_SZ;

        CP_WAIT0();            // B[kc] resident
        __syncthreads();       // prev compute done -> A buf + other B buf reusable

        // ---- prefetch B[kc+1] ----
        if (kc < 7){
            uint32_t bdst = sb + SM_B0 + ((kc+1) & 1)*B_BUF_SZ + bn*80 + hb*32;
            const unsigned short* src_h = g_Wt_hi + bn*256 + (kc+1)*32 + hb*16;
            const unsigned short* src_l = g_Wt_lo + bn*256 + (kc+1)*32 + hb*16;
            cp16(bdst,              src_h);
            cp16(bdst + 16,         src_h + 8);
            cp16(bdst + 20480,      src_l);
            cp16(bdst + 20480 + 16, src_l + 8);
            CP_COMMIT();
        }

        // ---- convert prefetched A[kc] -> smem ----
        {
            unsigned short h[8], l[8];
            split1(apre0.x, h[0], l[0]); split1(apre0.y, h[1], l[1]);
            split1(apre0.z, h[2], l[2]); split1(apre0.w, h[3], l[3]);
            split1(apre1.x, h[4], l[4]); split1(apre1.y, h[5], l[5]);
            split1(apre1.z, h[6], l[6]); split1(apre1.w, h[7], l[7]);
            uint4 hh; hh.x = pack2(h[0],h[1]); hh.y = pack2(h[2],h[3]);
                      hh.z = pack2(h[4],h[5]); hh.w = pack2(h[6],h[7]);
            uint4 ll; ll.x = pack2(l[0],l[1]); ll.y = pack2(l[2],l[3]);
                      ll.z = pack2(l[4],l[5]); ll.w = pack2(l[6],l[7]);
            *(uint4*)(sm + SM_AHI + arow*80 + ac*16) = hh;
            *(uint4*)(sm + SM_ALO + arow*80 + ac*16) = ll;
        }
        // ---- prefetch A[kc+1] into regs (latency hidden by compute) ----
        if (kc < 7){
            const float* srcb = (kc+1 < 4) ? f1 : f2;
            const int ksrc = ((kc+1) & 3) * 32;
            const float* ap = srcb + (size_t)(row0g + arow)*DIM + ksrc + ac*8;
            apre0 = *(const float4*)ap; apre1 = *(const float4*)(ap + 4);
        }
        __syncthreads();       // A[kc] visible

        // ---- compute chunk kc ----
        #pragma unroll
        for (int ks = 0; ks < 2; ks++){
            const int kb = ks*16;
            uint32_t ah[2][4], al[2][4];
            #pragma unroll
            for (int mt = 0; mt < 2; mt++){
                int r = wm + mt*16 + wi + (grp & 1)*8;
                int c = kb + (grp >> 1)*8;
                uint32_t adr = sb + SM_AHI + r*80 + c*2;
                ldsm4(ah[mt], adr);
                ldsm4(al[mt], adr + (SM_ALO - SM_AHI));
            }
            #pragma unroll
            for (int np = 0; np < 4; np++){
                int n0 = wn + np*16;
                int rb = n0 + wi + (grp >> 1)*8;
                int cb = kb + (grp & 1)*8;
                uint32_t badr = bbase + rb*80 + cb*2;
                uint32_t bh[4], bl[4];
                ldsm4(bh, badr);
                ldsm4(bl, badr + 20480);
                #pragma unroll
                for (int mt = 0; mt < 2; mt++){
                    #pragma unroll
                    for (int nt = 0; nt < 2; nt++){
                        float* C = acc[mt][np*2 + nt];
                        mma_bf16(C, ah[mt], bh[nt*2], bh[nt*2+1]);
                        mma_bf16(C, al[mt], bh[nt*2], bh[nt*2+1]);
                        mma_bf16(C, ah[mt], bl[nt*2], bl[nt*2+1]);
                    }
                }
            }
        }
    }

    // ---- epilogue: write v|skip with bias ----
    const int gid = lane >> 2, tc = lane & 3;
    #pragma unroll
    for (int mt = 0; mt < 2; mt++){
        int r0 = row0g + wm + mt*16 + gid;
        #pragma unroll
        for (int np = 0; np < 4; np++){
            #pragma unroll
            for (int nt = 0; nt < 2; nt++){
                int col = wn + np*16 + nt*8 + tc*2;
                float* dst = (col < 128) ? g_v : g_skip;
                int cl = col & 127;
                float b0 = g_bcat[col], b1 = g_bcat[col + 1];
                float* C = acc[mt][np*2 + nt];
                float2 o0; o0.x = C[0] + b0; o0.y = C[1] + b1;
                float2 o1; o1.x = C[2] + b0; o1.y = C[3] + b1;
                *(float2*)(dst + (size_t)r0*OUTD + cl)       = o0;
                *(float2*)(dst + (size_t)(r0+8)*OUTD + cl)   = o1;
            }
        }
    }
}

// ---------------- attention-vector GEMM: [att1 | att2] = z @ Wa + ba ----------------
__global__ void __launch_bounds__(256) gemm_att(const float* __restrict__ f1,
                                                const float* __restrict__ f2in,
                                                int use_hidden2){
    const float* f2 = use_hidden2 ? g_hidden2 : f2in;
    __shared__ float As2[128][36];
    __shared__ float Bs[32][16];
    const int t = threadIdx.x;
    const int row0 = blockIdx.x * 128;
    const int my = t >> 1, tx = t & 1;
    float acc[8] = {0,0,0,0,0,0,0,0};

    for (int half = 0; half < 2; half++){
        const float* base = half ? f2 : f1;
        for (int kc = 0; kc < DIM; kc += 32){
            #pragma unroll
            for (int i = 0; i < 4; i++){
                int id = t + 256*i;
                int r = id >> 3, q = id & 7;
                float4 g = *(const float4*)(base + (size_t)(row0 + r)*DIM + kc + q*4);
                *(float4*)(&As2[r][q*4]) = g;
            }
            if (t < 128){
                int kk = t >> 2, j4 = (t & 3)*4;
                *(float4*)(&Bs[kk][j4]) = *(const float4*)(g_Wa + (half*DIM + kc + kk)*16 + j4);
            }
            __syncthreads();
            #pragma unroll
            for (int kk = 0; kk < 32; kk++){
                float a = As2[my][kk];
                float4 b0 = *(float4*)(&Bs[kk][tx*8]);
                float4 b1 = *(float4*)(&Bs[kk][tx*8 + 4]);
                acc[0] = fmaf(a, b0.x, acc[0]); acc[1] = fmaf(a, b0.y, acc[1]);
                acc[2] = fmaf(a, b0.z, acc[2]); acc[3] = fmaf(a, b0.w, acc[3]);
                acc[4] = fmaf(a, b1.x, acc[4]); acc[5] = fmaf(a, b1.y, acc[5]);
                acc[6] = fmaf(a, b1.z, acc[6]); acc[7] = fmaf(a, b1.w, acc[7]);
            }
            __syncthreads();
        }
    }

    int row = row0 + my;
    #pragma unroll
    for (int jj = 0; jj < 8; jj++){
        int j = tx*8 + jj;
        float v = acc[jj] + g_ba[j];
        if (j < HEADS) g_att1[row*HEADS + j] = v;
        else           g_att2[row*HEADS + (j-HEADS)] = v;
    }
}

// ---------------- fused edge pass (cfg): logits -> exp -> scatter sum & exp*v ----------------
__global__ void __launch_bounds__(256) edge_pass_cfg(const int* __restrict__ idx){
    int gt = blockIdx.x*blockDim.x + threadIdx.x;
    int e = gt >> 5, lane = gt & 31;
    if (e >= EDGES_TOT) return;
    int s = idx[2*e], tg = idx[2*e + 1];
    int base = (e >= NEDGE) ? NNODE : 0;
    float ex = 0.0f;
    if (lane < HEADS){
        float l = g_att1[(base+s)*HEADS + lane] + g_att2[(base+tg)*HEADS + lane];
        l = (l > 0.0f) ? l : NEG_SLOPE*l;
        ex = __expf(l);
        atomicAdd(&g_sumv[(base+tg)*HEADS + lane], ex);
    }
    float c = __shfl_sync(0xffffffffu, ex, lane >> 2);
    float4 v4 = *(const float4*)(g_v + (size_t)(base+s)*OUTD + lane*4);
    float4 m; m.x = c*v4.x; m.y = c*v4.y; m.z = c*v4.z; m.w = c*v4.w;
    float* p = g_agg + (size_t)(base+tg)*OUTD + lane*4;
    asm volatile("red.global.add.v4.f32 [%0], {%1,%2,%3,%4};"
                 :: "l"(p), "f"(m.x), "f"(m.y), "f"(m.z), "f"(m.w) : "memory");
}

// ---------------- fused edge pass (gkt): + edge-feature logits ----------------
__global__ void __launch_bounds__(256) edge_pass_gkt(const float* __restrict__ ef,
                                                     const int* __restrict__ idx,
                                                     const float* __restrict__ Wae,
                                                     const float* __restrict__ bae){
    __shared__ float sWt[8][132];   // transposed Wae: [h][k]
    for (int i = threadIdx.x; i < DIM*HEADS; i += 256){
        int k = i & 127, h = i >> 7;
        sWt[h][k] = Wae[k*HEADS + h];
    }
    __syncthreads();
    int e = (blockIdx.x*256 + threadIdx.x) >> 5;
    int lane = threadIdx.x & 31;
    if (e >= EDGES_TOT) return;

    float4 x = *(const float4*)(ef + (size_t)e*DIM + lane*4);
    float p8[8];
    #pragma unroll
    for (int h = 0; h < 8; h++){
        float4 w = *(const float4*)(&sWt[h][lane*4]);
        p8[h] = x.x*w.x + x.y*w.y + x.z*w.z + x.w*w.w;
    }
    float ae = 0.0f;
    #pragma unroll
    for (int h = 0; h < 8; h++){
        float v = p8[h];
        v += __shfl_xor_sync(0xffffffffu, v, 16);
        v += __shfl_xor_sync(0xffffffffu, v, 8);
        v += __shfl_xor_sync(0xffffffffu, v, 4);
        v += __shfl_xor_sync(0xffffffffu, v, 2);
        v += __shfl_xor_sync(0xffffffffu, v, 1);
        if (lane == h) ae = v;
    }
    int s = idx[2*e], tg = idx[2*e + 1];
    int base = (e >= NEDGE) ? NNODE : 0;
    float ex = 0.0f;
    if (lane < HEADS){
        float l = g_att1[(base+s)*HEADS + lane] + g_att2[(base+tg)*HEADS + lane]
                  + ae + bae[lane];
        l = (l > 0.0f) ? l : NEG_SLOPE*l;
        ex = __expf(l);
        atomicAdd(&g_sumv[(base+tg)*HEADS + lane], ex);
    }
    float c = __shfl_sync(0xffffffffu, ex, lane >> 2);
    float4 v4 = *(const float4*)(g_v + (size_t)(base+s)*OUTD + lane*4);
    float4 m; m.x = c*v4.x; m.y = c*v4.y; m.z = c*v4.z; m.w = c*v4.w;
    float* p = g_agg + (size_t)(base+tg)*OUTD + lane*4;
    asm volatile("red.global.add.v4.f32 [%0], {%1,%2,%3,%4};"
                 :: "l"(p), "f"(m.x), "f"(m.y), "f"(m.z), "f"(m.w) : "memory");
}

// ---------------- finalize: relu(agg/sumv + skip); reset agg/sumv race-free ----------------
__global__ void finalize(float* __restrict__ dstin, int to_hidden2){
    int i = blockIdx.x*blockDim.x + threadIdx.x;
    if (i >= NODES_TOT*OUTD/4) return;
    float* dst = to_hidden2 ? g_hidden2 : dstin;
    int node = i >> 5;
    int head = (i & 31) >> 2;
    float sv = g_sumv[node*HEADS + head];
    __syncwarp();
    if ((i & 3) == 0) g_sumv[node*HEADS + head] = 0.0f;
    float inv = (sv != 0.0f) ? (1.0f / sv) : 0.0f;
    float4 a = ((const float4*)g_agg)[i];
    float4 s = ((const float4*)g_skip)[i];
    float4 o;
    o.x = fmaxf(fmaf(a.x, inv, s.x), 0.0f);
    o.y = fmaxf(fmaf(a.y, inv, s.y), 0.0f);
    o.z = fmaxf(fmaf(a.z, inv, s.z), 0.0f);
    o.w = fmaxf(fmaf(a.w, inv, s.w), 0.0f);
    ((float4*)dst)[i] = o;
    float4 z; z.x = 0.0f; z.y = 0.0f; z.z = 0.0f; z.w = 0.0f;
    ((float4*)g_agg)[i] = z;
}

// ---------------- launch ----------------
extern "C" void kernel_launch(void* const* d_in, const int* in_sizes, int n_in,
                              void* d_out, int out_size){
    const float* node_fts     = (const float*)d_in[0];
    const float* gkt_edge_fts = (const float*)d_in[1];
    const float* hidden       = (const float*)d_in[2];
    const int*   cfg_idx      = (const int*)d_in[3];
    const int*   gkt_idx      = (const int*)d_in[4];
    const float* Wm    = (const float*)d_in[5];
    const float* bm    = (const float*)d_in[6];
    const float* Wskip = (const float*)d_in[7];
    const float* bskip = (const float*)d_in[8];
    const float* Wa1   = (const float*)d_in[9];
    const float* ba1   = (const float*)d_in[10];
    const float* Wa2   = (const float*)d_in[11];
    const float* ba2   = (const float*)d_in[12];
    const float* Wae   = (const float*)d_in[13];
    const float* bae   = (const float*)d_in[14];
    float* out = (float*)d_out;

    static int smem_set = 0;
    if (!smem_set){
        cudaFuncSetAttribute(gemm_node_mma, cudaFuncAttributeMaxDynamicSharedMemorySize, GEMM_SMEM);
        smem_set = 1;
    }

    const int TB = 256;

    build_w<<<(256*256 + TB-1)/TB, TB>>>(Wm, bm, Wskip, bskip, Wa1, ba1, Wa2, ba2);   // 0

    // ===== stage 1 (cfg): z = [node_fts | hidden] =====
    gemm_att<<<NODES_TOT/128, TB>>>(node_fts, hidden, 0);                              // 1
    gemm_node_mma<<<NODES_TOT/128, 512, GEMM_SMEM>>>(node_fts, hidden, 0);             // 2
    edge_pass_cfg<<<(EDGES_TOT*32)/TB, TB>>>(cfg_idx);                                 // 3 <- ncu capture
    finalize<<<(NODES_TOT*OUTD/4)/TB, TB>>>(out, 1);   // -> g_hidden2                 // 4

    // ===== stage 2 (gkt): z = [node_fts | cfg_hidden] =====
    gemm_att<<<NODES_TOT/128, TB>>>(node_fts, nullptr, 1);                             // 5
    gemm_node_mma<<<NODES_TOT/128, 512, GEMM_SMEM>>>(node_fts, nullptr, 1);            // 6
    edge_pass_gkt<<<(EDGES_TOT*32)/TB, TB>>>(gkt_edge_fts, gkt_idx, Wae, bae);         // 7
    finalize<<<(NODES_TOT*OUTD/4)/TB, TB>>>(out, 0);   // -> d_out                     // 8
}